// round 6
// baseline (speedup 1.0000x reference)
#include <cuda_runtime.h>
#include <cuda_bf16.h>
#include <math.h>
#include <stdint.h>

#define NN 50000
#define EE 200000
#define E2 (EE + NN)
#define HD 128

// ---------------- scratch (static device globals; no allocation) ----------------
__device__ int   g_down[NN];
__device__ __align__(16) float g_h[NN * HD];
__device__ __align__(16) float g_h2[NN * HD];
__device__ __align__(16) float g_agg[(size_t)NN * 512];
__device__ __align__(16) float g_als[NN * 4];
__device__ __align__(16) float g_ald[NN * 4];
__device__ int   g_cnt[NN];
__device__ int   g_rowtmp[NN];
__device__ int   g_bsum[64];
__device__ int   g_rowptr[NN + 1];
__device__ int   g_cursor[NN];
__device__ int   g_csrsrc[E2];
__device__ __align__(16) float g_p[NN * HD];
__device__ __align__(16) float g_q[NN * HD];
__device__ __align__(16) float g_wsrc[3 * 4 * 128];
__device__ __align__(16) float g_wdst[3 * 4 * 128];
__device__ __align__(16) float g_wperm[3 * 512 * 128];
__device__ __align__(16) float g_bnscale[3 * 128];
__device__ __align__(16) float g_bnshift[3 * 128];

// ---------------- small helpers ----------------
__global__ void k_zero_misc() {
    int i = blockIdx.x * blockDim.x + threadIdx.x;
    if (i < NN) { g_down[i] = 0; g_cnt[i] = 0; }
}

__global__ void k_down(const int* __restrict__ src, const int* __restrict__ dst,
                       const int* __restrict__ shock) {
    int e = blockIdx.x * blockDim.x + threadIdx.x;
    if (e >= EE) return;
    if (shock[src[e]] != 0) g_down[dst[e]] = 1;
}

__global__ void k_count(const int* __restrict__ dst) {
    int e = blockIdx.x * blockDim.x + threadIdx.x;
    if (e >= E2) return;
    int d = (e < EE) ? dst[e] : (e - EE);
    atomicAdd(&g_cnt[d], 1);
}

__global__ void k_scan1() {
    __shared__ int sh[1024];
    int tid = threadIdx.x;
    int i = blockIdx.x * 1024 + tid;
    int v = (i < NN) ? g_cnt[i] : 0;
    sh[tid] = v;
    __syncthreads();
    for (int off = 1; off < 1024; off <<= 1) {
        int t = (tid >= off) ? sh[tid - off] : 0;
        __syncthreads();
        sh[tid] += t;
        __syncthreads();
    }
    int incl = sh[tid];
    if (i < NN) g_rowtmp[i] = incl - v;
    if (tid == 1023) g_bsum[blockIdx.x] = incl;
}

__global__ void k_scan2(int nb) {
    if (threadIdx.x == 0 && blockIdx.x == 0) {
        int acc = 0;
        for (int b = 0; b < nb; b++) { int t = g_bsum[b]; g_bsum[b] = acc; acc += t; }
    }
}

__global__ void k_scan3() {
    int i = blockIdx.x * blockDim.x + threadIdx.x;
    if (i >= NN) return;
    int r = g_rowtmp[i] + g_bsum[i >> 10];
    g_rowptr[i] = r;
    g_cursor[i] = r;
    if (i == NN - 1) g_rowptr[NN] = E2;
}

__global__ void k_scatter(const int* __restrict__ src, const int* __restrict__ dst) {
    int e = blockIdx.x * blockDim.x + threadIdx.x;
    if (e >= E2) return;
    int s, d;
    if (e < EE) { s = src[e]; d = dst[e]; } else { s = e - EE; d = e - EE; }
    int pos = atomicAdd(&g_cursor[d], 1);
    g_csrsrc[pos] = s;
}

// ---------------- node encoder: xa@W + b -> LN -> relu ----------------
__global__ void k_encoder(const float* __restrict__ x, const int* __restrict__ shock,
                          const float* __restrict__ W, const float* __restrict__ b,
                          const float* __restrict__ lng, const float* __restrict__ lnb,
                          float* __restrict__ hout) {
    int n = blockIdx.x;
    int t = threadIdx.x;
    __shared__ float xa[18];
    __shared__ float r1[4], r2[4];
    if (t < 16)      xa[t]  = x[n * 16 + t];
    else if (t == 16) xa[16] = (float)shock[n];
    else if (t == 17) xa[17] = (float)g_down[n];
    __syncthreads();
    float v = b[t];
#pragma unroll
    for (int j = 0; j < 18; j++) v += xa[j] * W[j * HD + t];
    float s = v, s2 = v * v;
    for (int off = 16; off > 0; off >>= 1) {
        s  += __shfl_down_sync(0xffffffffu, s,  off);
        s2 += __shfl_down_sync(0xffffffffu, s2, off);
    }
    if ((t & 31) == 0) { r1[t >> 5] = s; r2[t >> 5] = s2; }
    __syncthreads();
    float mu  = (r1[0] + r1[1] + r1[2] + r1[3]) * (1.0f / HD);
    float var = (r2[0] + r2[1] + r2[2] + r2[3]) * (1.0f / HD) - mu * mu;
    float y = (v - mu) * rsqrtf(var + 1e-5f) * lng[t] + lnb[t];
    hout[n * HD + t] = fmaxf(y, 0.0f);
}

// ---------------- weight prep ----------------
// Wa = W @ att per layer/head (for logits from h)
__global__ void k_watt(const float* __restrict__ gw,
                       const float* __restrict__ as_, const float* __restrict__ ad_) {
    int l = blockIdx.x, h = blockIdx.y;
    int k = threadIdx.x;
    __shared__ float s_as[128], s_ad[128];
    s_as[k] = as_[(l * 4 + h) * 128 + k];
    s_ad[k] = ad_[(l * 4 + h) * 128 + k];
    __syncthreads();
    const float* wrow = gw + ((size_t)l * 128 + k) * 512 + h * 128;
    float ss = 0.0f, sd = 0.0f;
#pragma unroll 8
    for (int cc = 0; cc < 128; cc++) {
        float w = wrow[cc];
        ss += w * s_as[cc];
        sd += w * s_ad[cc];
    }
    g_wsrc[(l * 4 + h) * 128 + k] = ss;
    g_wdst[(l * 4 + h) * 128 + k] = sd;
}

// W' permuted for post-aggregation GEMM: wperm[l][hd*128+k][c] = 0.25 * W[l][k][hd*128+c]
__global__ void k_permw(const float* __restrict__ gw) {
    int l = blockIdx.x;
    int kk = blockIdx.y;           // 0..511
    int c = threadIdx.x;           // 0..127
    int k = kk & 127, hd = kk >> 7;
    g_wperm[((size_t)l * 512 + kk) * 128 + c] =
        0.25f * gw[((size_t)l * 128 + k) * 512 + hd * 128 + c];
}

// per-channel BN+bias folded: scale = g/sqrt(v+eps); shift = (bias - m)*scale + b
__global__ void k_bnprep(const float* __restrict__ bias, const float* __restrict__ bng,
                         const float* __restrict__ bnb, const float* __restrict__ bnm,
                         const float* __restrict__ bnv) {
    int l = blockIdx.x, c = threadIdx.x;
    int i = l * 128 + c;
    float sc = bng[i] * rsqrtf(bnv[i] + 1e-5f);
    g_bnscale[i] = sc;
    g_bnshift[i] = (bias[i] - bnm[i]) * sc + bnb[i];
}

// ---------------- tf32 tensor-core GEMM with optional BN epilogue ----------------
__device__ __forceinline__ float to_tf32(float x) {
    float r;
    asm("cvt.rna.tf32.f32 %0, %1;" : "=f"(r) : "f"(x));
    return r;
}

__device__ __forceinline__ void mma_tf32(float* d, const uint32_t* a, const uint32_t* b) {
    asm volatile(
        "mma.sync.aligned.m16n8k8.row.col.f32.tf32.tf32.f32 "
        "{%0,%1,%2,%3}, {%4,%5,%6,%7}, {%8,%9}, {%0,%1,%2,%3};\n"
        : "+f"(d[0]), "+f"(d[1]), "+f"(d[2]), "+f"(d[3])
        : "r"(a[0]), "r"(a[1]), "r"(a[2]), "r"(a[3]), "r"(b[0]), "r"(b[1]));
}

__global__ __launch_bounds__(256) void gemm_tf32(const float* __restrict__ A,
                                                 const float* __restrict__ B,
                                                 float* __restrict__ C,
                                                 int M, int N, int K,
                                                 const float* __restrict__ escale,
                                                 const float* __restrict__ eshift,
                                                 int do_relu) {
    __shared__ __align__(16) float As[128][36];
    __shared__ __align__(16) float Bs[32][136];
    int tid = threadIdx.x;
    int m0 = blockIdx.x * 128, n0 = blockIdx.y * 128;
    int lane = tid & 31, wid = tid >> 5;
    int mbase = (wid & 1) * 64;
    int nbase = (wid >> 1) * 32;
    int r = lane >> 2, qc = lane & 3;

    float acc[4][4][4];
#pragma unroll
    for (int i = 0; i < 4; i++)
#pragma unroll
        for (int j = 0; j < 4; j++)
#pragma unroll
            for (int q = 0; q < 4; q++) acc[i][j][q] = 0.0f;

    for (int kc = 0; kc < K; kc += 32) {
        __syncthreads();
#pragma unroll
        for (int i = 0; i < 4; i++) {
            int l4 = tid + i * 256;
            int row = l4 >> 3, c4 = (l4 & 7) << 2;
            float4 v = make_float4(0.f, 0.f, 0.f, 0.f);
            int gr = m0 + row;
            if (gr < M) v = *(const float4*)&A[(size_t)gr * K + kc + c4];
            v.x = to_tf32(v.x); v.y = to_tf32(v.y);
            v.z = to_tf32(v.z); v.w = to_tf32(v.w);
            *(float4*)&As[row][c4] = v;
        }
#pragma unroll
        for (int i = 0; i < 4; i++) {
            int l4 = tid + i * 256;
            int row = l4 >> 5, c4 = (l4 & 31) << 2;
            float4 v = *(const float4*)&B[(size_t)(kc + row) * N + n0 + c4];
            v.x = to_tf32(v.x); v.y = to_tf32(v.y);
            v.z = to_tf32(v.z); v.w = to_tf32(v.w);
            *(float4*)&Bs[row][c4] = v;
        }
        __syncthreads();

#pragma unroll
        for (int k0 = 0; k0 < 32; k0 += 8) {
            uint32_t af[4][4], bf[4][2];
#pragma unroll
            for (int am = 0; am < 4; am++) {
                int row0 = mbase + am * 16 + r;
                af[am][0] = __float_as_uint(As[row0][k0 + qc]);
                af[am][1] = __float_as_uint(As[row0 + 8][k0 + qc]);
                af[am][2] = __float_as_uint(As[row0][k0 + qc + 4]);
                af[am][3] = __float_as_uint(As[row0 + 8][k0 + qc + 4]);
            }
#pragma unroll
            for (int an = 0; an < 4; an++) {
                int col0 = nbase + an * 8 + r;
                bf[an][0] = __float_as_uint(Bs[k0 + qc][col0]);
                bf[an][1] = __float_as_uint(Bs[k0 + qc + 4][col0]);
            }
#pragma unroll
            for (int am = 0; am < 4; am++)
#pragma unroll
                for (int an = 0; an < 4; an++)
                    mma_tf32(acc[am][an], af[am], bf[an]);
        }
    }

#pragma unroll
    for (int am = 0; am < 4; am++) {
        int row = m0 + mbase + am * 16 + r;
#pragma unroll
        for (int an = 0; an < 4; an++) {
            int col = n0 + nbase + an * 8 + 2 * qc;
            float v0 = acc[am][an][0], v1 = acc[am][an][1];
            float v2 = acc[am][an][2], v3 = acc[am][an][3];
            if (escale) {
                float s0 = escale[col], s1 = escale[col + 1];
                float h0 = eshift[col], h1 = eshift[col + 1];
                v0 = v0 * s0 + h0; v1 = v1 * s1 + h1;
                v2 = v2 * s0 + h0; v3 = v3 * s1 + h1;
                if (do_relu) {
                    v0 = fmaxf(v0, 0.f); v1 = fmaxf(v1, 0.f);
                    v2 = fmaxf(v2, 0.f); v3 = fmaxf(v3, 0.f);
                }
            }
            if (row < M)
                *(float2*)&C[(size_t)row * N + col] = make_float2(v0, v1);
            if (row + 8 < M)
                *(float2*)&C[(size_t)(row + 8) * N + col] = make_float2(v2, v3);
        }
    }
}

// ---------------- logits from h directly: als = h @ Wa ----------------
__global__ void k_logits2(const float* __restrict__ h, int l) {
    int node = blockIdx.x * 4 + (threadIdx.x >> 5);
    int lane = threadIdx.x & 31;
    if (node >= NN) return;
    float4 hv = *(const float4*)&h[(size_t)node * HD + lane * 4];
#pragma unroll
    for (int hh = 0; hh < 4; hh++) {
        float4 ws = *(const float4*)&g_wsrc[(l * 4 + hh) * 128 + lane * 4];
        float4 wd = *(const float4*)&g_wdst[(l * 4 + hh) * 128 + lane * 4];
        float ds = hv.x * ws.x + hv.y * ws.y + hv.z * ws.z + hv.w * ws.w;
        float dd = hv.x * wd.x + hv.y * wd.y + hv.z * wd.z + hv.w * wd.w;
#pragma unroll
        for (int off = 16; off > 0; off >>= 1) {
            ds += __shfl_down_sync(0xffffffffu, ds, off);
            dd += __shfl_down_sync(0xffffffffu, dd, off);
        }
        if (lane == 0) { g_als[node * 4 + hh] = ds; g_ald[node * 4 + hh] = dd; }
    }
}

// ------- gather v2: softmax over edges, aggregate h[src] (128f) per head -> agg[N,512] -------
__global__ void k_gather2(const float* __restrict__ h, float* __restrict__ agg) {
    int node = blockIdx.x * 4 + (threadIdx.x >> 5);
    int lane = threadIdx.x & 31;
    if (node >= NN) return;
    int beg = g_rowptr[node], end = g_rowptr[node + 1];
    float4 ald4 = *(const float4*)&g_ald[node * 4];

    // pass 1: per-head max, lane-parallel over edges
    float4 mx = make_float4(-1e30f, -1e30f, -1e30f, -1e30f);
    for (int i = beg + lane; i < end; i += 32) {
        int s = g_csrsrc[i];
        float4 a = *(const float4*)&g_als[s * 4];
        a.x += ald4.x; a.y += ald4.y; a.z += ald4.z; a.w += ald4.w;
        a.x = (a.x >= 0.f) ? a.x : 0.2f * a.x;
        a.y = (a.y >= 0.f) ? a.y : 0.2f * a.y;
        a.z = (a.z >= 0.f) ? a.z : 0.2f * a.z;
        a.w = (a.w >= 0.f) ? a.w : 0.2f * a.w;
        mx.x = fmaxf(mx.x, a.x); mx.y = fmaxf(mx.y, a.y);
        mx.z = fmaxf(mx.z, a.z); mx.w = fmaxf(mx.w, a.w);
    }
#pragma unroll
    for (int off = 16; off > 0; off >>= 1) {
        mx.x = fmaxf(mx.x, __shfl_xor_sync(0xffffffffu, mx.x, off));
        mx.y = fmaxf(mx.y, __shfl_xor_sync(0xffffffffu, mx.y, off));
        mx.z = fmaxf(mx.z, __shfl_xor_sync(0xffffffffu, mx.z, off));
        mx.w = fmaxf(mx.w, __shfl_xor_sync(0xffffffffu, mx.w, off));
    }

    // pass 2: weights (computed redundantly per lane) + vector accumulate of h[s]
    float4 acc0 = make_float4(0, 0, 0, 0), acc1 = acc0, acc2 = acc0, acc3 = acc0;
    float4 sum = make_float4(0, 0, 0, 0);
    for (int i = beg; i < end; i++) {
        int s = g_csrsrc[i];
        float4 a = *(const float4*)&g_als[s * 4];   // broadcast
        a.x += ald4.x; a.y += ald4.y; a.z += ald4.z; a.w += ald4.w;
        a.x = (a.x >= 0.f) ? a.x : 0.2f * a.x;
        a.y = (a.y >= 0.f) ? a.y : 0.2f * a.y;
        a.z = (a.z >= 0.f) ? a.z : 0.2f * a.z;
        a.w = (a.w >= 0.f) ? a.w : 0.2f * a.w;
        float w0 = expf(a.x - mx.x), w1 = expf(a.y - mx.y);
        float w2 = expf(a.z - mx.z), w3 = expf(a.w - mx.w);
        sum.x += w0; sum.y += w1; sum.z += w2; sum.w += w3;
        float4 v = *(const float4*)&h[(size_t)s * HD + lane * 4];
        acc0.x += w0 * v.x; acc0.y += w0 * v.y; acc0.z += w0 * v.z; acc0.w += w0 * v.w;
        acc1.x += w1 * v.x; acc1.y += w1 * v.y; acc1.z += w1 * v.z; acc1.w += w1 * v.w;
        acc2.x += w2 * v.x; acc2.y += w2 * v.y; acc2.z += w2 * v.z; acc2.w += w2 * v.w;
        acc3.x += w3 * v.x; acc3.y += w3 * v.y; acc3.z += w3 * v.z; acc3.w += w3 * v.w;
    }
    float i0 = 1.0f / (sum.x + 1e-16f);
    float i1 = 1.0f / (sum.y + 1e-16f);
    float i2 = 1.0f / (sum.z + 1e-16f);
    float i3 = 1.0f / (sum.w + 1e-16f);
    float* ap = agg + (size_t)node * 512 + lane * 4;
    *(float4*)(ap)       = make_float4(acc0.x * i0, acc0.y * i0, acc0.z * i0, acc0.w * i0);
    *(float4*)(ap + 128) = make_float4(acc1.x * i1, acc1.y * i1, acc1.z * i1, acc1.w * i1);
    *(float4*)(ap + 256) = make_float4(acc2.x * i2, acc2.y * i2, acc2.z * i2, acc2.w * i2);
    *(float4*)(ap + 384) = make_float4(acc3.x * i3, acc3.y * i3, acc3.z * i3, acc3.w * i3);
}

// ------- fused edge MLP v2: 16 edges/block, register-tiled z1@W2 ---------------
__global__ __launch_bounds__(256) void k_edge_mlp2(
        const int* __restrict__ src, const int* __restrict__ dst,
        const float* __restrict__ eattr,
        const float* __restrict__ em1b, const float* __restrict__ wc,
        const float* __restrict__ lng, const float* __restrict__ lnb,
        const float* __restrict__ w2, const float* __restrict__ b2,
        const float* __restrict__ w3, const float* __restrict__ b3,
        float* __restrict__ out) {
    __shared__ float sz1[16][128];
    __shared__ float spart[4][16][64];
    __shared__ float sea[2][8];
    __shared__ float red1[2][4], red2[2][4];

    int tid = threadIdx.x;
    int e_base = blockIdx.x * 16;
    int t = tid & 127, half = tid >> 7;

    for (int g = 0; g < 8; g++) {
        int el = g * 2 + half;
        int e = e_base + el;
        int s = src[e], d = dst[e];
        if (t < 8) sea[half][t] = eattr[e * 8 + t];
        __syncthreads();
        float v = g_p[s * HD + t] + g_q[d * HD + t] + em1b[t];
#pragma unroll
        for (int j = 0; j < 8; j++) v += sea[half][j] * wc[j * HD + t];
        float su = v, sq = v * v;
#pragma unroll
        for (int off = 16; off > 0; off >>= 1) {
            su += __shfl_down_sync(0xffffffffu, su, off);
            sq += __shfl_down_sync(0xffffffffu, sq, off);
        }
        if ((t & 31) == 0) { red1[half][t >> 5] = su; red2[half][t >> 5] = sq; }
        __syncthreads();
        float mu  = (red1[half][0] + red1[half][1] + red1[half][2] + red1[half][3]) * (1.0f / HD);
        float var = (red2[half][0] + red2[half][1] + red2[half][2] + red2[half][3]) * (1.0f / HD) - mu * mu;
        float y = (v - mu) * rsqrtf(var + 1e-5f) * lng[t] + lnb[t];
        sz1[el][t] = fmaxf(y, 0.0f);
    }
    __syncthreads();

    {
        int o4 = (tid & 15) * 4;
        int eg = (tid >> 4) & 3;
        int ks = tid >> 6;
        float4 a0 = make_float4(0, 0, 0, 0), a1 = a0, a2 = a0, a3 = a0;
        int kbeg = ks * 32;
#pragma unroll 8
        for (int k = kbeg; k < kbeg + 32; k++) {
            float4 w4 = *(const float4*)&w2[k * 64 + o4];
            float z0 = sz1[eg * 4 + 0][k];
            float z1v = sz1[eg * 4 + 1][k];
            float z2v = sz1[eg * 4 + 2][k];
            float z3v = sz1[eg * 4 + 3][k];
            a0.x += z0 * w4.x;  a0.y += z0 * w4.y;  a0.z += z0 * w4.z;  a0.w += z0 * w4.w;
            a1.x += z1v * w4.x; a1.y += z1v * w4.y; a1.z += z1v * w4.z; a1.w += z1v * w4.w;
            a2.x += z2v * w4.x; a2.y += z2v * w4.y; a2.z += z2v * w4.z; a2.w += z2v * w4.w;
            a3.x += z3v * w4.x; a3.y += z3v * w4.y; a3.z += z3v * w4.z; a3.w += z3v * w4.w;
        }
        *(float4*)&spart[ks][eg * 4 + 0][o4] = a0;
        *(float4*)&spart[ks][eg * 4 + 1][o4] = a1;
        *(float4*)&spart[ks][eg * 4 + 2][o4] = a2;
        *(float4*)&spart[ks][eg * 4 + 3][o4] = a3;
    }
    __syncthreads();

    {
        int e2 = tid >> 4;
        int ob = (tid & 15) * 4;
        float val = 0.0f;
#pragma unroll
        for (int i = 0; i < 4; i++) {
            int o = ob + i;
            float ssum = spart[0][e2][o] + spart[1][e2][o] + spart[2][e2][o] + spart[3][e2][o];
            float z2 = fmaxf(ssum + b2[o], 0.0f);
            val += z2 * w3[o];
        }
#pragma unroll
        for (int off = 8; off > 0; off >>= 1)
            val += __shfl_down_sync(0xffffffffu, val, off, 16);
        if ((tid & 15) == 0) out[e_base + e2] = val + b3[0];
    }
}

// ---------------- launch ----------------
extern "C" void kernel_launch(void* const* d_in, const int* in_sizes, int n_in,
                              void* d_out, int out_size) {
    const float* x       = (const float*)d_in[0];
    const int*   ei      = (const int*)d_in[1];
    const float* eattr   = (const float*)d_in[2];
    const int*   shock   = (const int*)d_in[3];
    const float* enc_w   = (const float*)d_in[4];
    const float* enc_b   = (const float*)d_in[5];
    const float* enc_lng = (const float*)d_in[6];
    const float* enc_lnb = (const float*)d_in[7];
    const float* gat_w   = (const float*)d_in[8];
    const float* att_src = (const float*)d_in[9];
    const float* att_dst = (const float*)d_in[10];
    const float* gat_bias= (const float*)d_in[11];
    const float* bn_g    = (const float*)d_in[12];
    const float* bn_b    = (const float*)d_in[13];
    const float* bn_m    = (const float*)d_in[14];
    const float* bn_v    = (const float*)d_in[15];
    const float* em1_w   = (const float*)d_in[16];
    const float* em1_b   = (const float*)d_in[17];
    const float* em_lng  = (const float*)d_in[18];
    const float* em_lnb  = (const float*)d_in[19];
    const float* em2_w   = (const float*)d_in[20];
    const float* em2_b   = (const float*)d_in[21];
    const float* em3_w   = (const float*)d_in[22];
    const float* em3_b   = (const float*)d_in[23];
    const int* src = ei;
    const int* dst = ei + EE;
    float* out = (float*)d_out;

    float *ph, *ph2, *pagg, *pp, *pq, *pwperm, *pbnsc, *pbnsh;
    cudaGetSymbolAddress((void**)&ph,    g_h);
    cudaGetSymbolAddress((void**)&ph2,   g_h2);
    cudaGetSymbolAddress((void**)&pagg,  g_agg);
    cudaGetSymbolAddress((void**)&pp,    g_p);
    cudaGetSymbolAddress((void**)&pq,    g_q);
    cudaGetSymbolAddress((void**)&pwperm, g_wperm);
    cudaGetSymbolAddress((void**)&pbnsc, g_bnscale);
    cudaGetSymbolAddress((void**)&pbnsh, g_bnshift);

    // graph prep: downstream flags + CSR by destination (with self-loops)
    k_zero_misc<<<(NN + 255) / 256, 256>>>();
    k_down<<<(EE + 255) / 256, 256>>>(src, dst, shock);
    k_count<<<(E2 + 255) / 256, 256>>>(dst);
    int nb = (NN + 1023) / 1024;
    k_scan1<<<nb, 1024>>>();
    k_scan2<<<1, 32>>>(nb);
    k_scan3<<<(NN + 255) / 256, 256>>>();
    k_scatter<<<(E2 + 255) / 256, 256>>>(src, dst);

    // weight prep
    k_watt<<<dim3(3, 4), 128>>>(gat_w, att_src, att_dst);
    k_permw<<<dim3(3, 512), 128>>>(gat_w);
    k_bnprep<<<3, 128>>>(gat_bias, bn_g, bn_b, bn_m, bn_v);

    // node encoder
    k_encoder<<<NN, 128>>>(x, shock, enc_w, enc_b, enc_lng, enc_lnb, ph);

    // 3 GAT layers: logits -> aggregate h -> GEMM(+BN fused)
    float* hin = ph;
    float* hout = ph2;
    int gx = (NN + 127) / 128;
    for (int l = 0; l < 3; l++) {
        k_logits2<<<(NN + 3) / 4, 128>>>(hin, l);
        k_gather2<<<(NN + 3) / 4, 128>>>(hin, pagg);
        gemm_tf32<<<dim3(gx, 1), 256>>>(pagg, pwperm + (size_t)l * 512 * 128, hout,
                                        NN, 128, 512,
                                        pbnsc + l * 128, pbnsh + l * 128, (l < 2) ? 1 : 0);
        float* tmp = hin; hin = hout; hout = tmp;
    }
    // hin now holds the final node embeddings

    // edge MLP first layer factored: p = h @ W_a, q = h @ W_b
    gemm_tf32<<<dim3(gx, 1), 256>>>(hin, em1_w,            pp, NN, HD, HD, nullptr, nullptr, 0);
    gemm_tf32<<<dim3(gx, 1), 256>>>(hin, em1_w + 128 * HD, pq, NN, HD, HD, nullptr, nullptr, 0);

    // fused edge predictor (EE = 12500 * 16 exactly)
    k_edge_mlp2<<<EE / 16, 256>>>(src, dst, eattr, em1_b, em1_w + 256 * HD,
                                  em_lng, em_lnb, em2_w, em2_b, em3_w, em3_b, out);
}

// round 9
// speedup vs baseline: 1.1114x; 1.1114x over previous
#include <cuda_runtime.h>
#include <cuda_bf16.h>
#include <cuda_fp16.h>
#include <math.h>
#include <stdint.h>

#define NN 50000
#define EE 200000
#define E2 (EE + NN)
#define HD 128

// ---------------- scratch (static device globals; no allocation) ----------------
__device__ int   g_down[NN];
__device__ __align__(16) float g_h[NN * HD];
__device__ __align__(16) float g_h2[NN * HD];
__device__ __align__(16) float g_agg[(size_t)NN * 512];
__device__ __align__(16) float g_als[NN * 4];
__device__ __align__(16) float g_ald[NN * 4];
__device__ int   g_cnt[NN];
__device__ int   g_rowtmp[NN];
__device__ int   g_bsum[64];
__device__ int   g_rowptr[NN + 1];
__device__ int   g_cursor[NN];
__device__ int   g_csrsrc[E2];
__device__ __align__(16) float g_p[NN * HD];
__device__ __align__(16) float g_q[NN * HD];
__device__ __align__(16) float g_wsrc[3 * 4 * 128];
__device__ __align__(16) float g_wdst[3 * 4 * 128];
__device__ __align__(16) __half g_wpermh[3 * 128 * 512];  // [l][cout][kk]
__device__ __align__(16) __half g_emp[128 * 128];         // [n][k]
__device__ __align__(16) __half g_emq[128 * 128];         // [n][k]
__device__ __align__(16) float g_bnscale[3 * 128];
__device__ __align__(16) float g_bnshift[3 * 128];

// ---------------- small helpers ----------------
__global__ void k_zero_misc() {
    int i = blockIdx.x * blockDim.x + threadIdx.x;
    if (i < NN) { g_down[i] = 0; g_cnt[i] = 0; }
}

__global__ void k_down(const int* __restrict__ src, const int* __restrict__ dst,
                       const int* __restrict__ shock) {
    int e = blockIdx.x * blockDim.x + threadIdx.x;
    if (e >= EE) return;
    if (shock[src[e]] != 0) g_down[dst[e]] = 1;
}

__global__ void k_count(const int* __restrict__ dst) {
    int e = blockIdx.x * blockDim.x + threadIdx.x;
    if (e >= E2) return;
    int d = (e < EE) ? dst[e] : (e - EE);
    atomicAdd(&g_cnt[d], 1);
}

__global__ void k_scan1() {
    __shared__ int sh[1024];
    int tid = threadIdx.x;
    int i = blockIdx.x * 1024 + tid;
    int v = (i < NN) ? g_cnt[i] : 0;
    sh[tid] = v;
    __syncthreads();
    for (int off = 1; off < 1024; off <<= 1) {
        int t = (tid >= off) ? sh[tid - off] : 0;
        __syncthreads();
        sh[tid] += t;
        __syncthreads();
    }
    int incl = sh[tid];
    if (i < NN) g_rowtmp[i] = incl - v;
    if (tid == 1023) g_bsum[blockIdx.x] = incl;
}

__global__ void k_scan2(int nb) {
    if (threadIdx.x == 0 && blockIdx.x == 0) {
        int acc = 0;
        for (int b = 0; b < nb; b++) { int t = g_bsum[b]; g_bsum[b] = acc; acc += t; }
    }
}

__global__ void k_scan3() {
    int i = blockIdx.x * blockDim.x + threadIdx.x;
    if (i >= NN) return;
    int r = g_rowtmp[i] + g_bsum[i >> 10];
    g_rowptr[i] = r;
    g_cursor[i] = r;
    if (i == NN - 1) g_rowptr[NN] = E2;
}

__global__ void k_scatter(const int* __restrict__ src, const int* __restrict__ dst) {
    int e = blockIdx.x * blockDim.x + threadIdx.x;
    if (e >= E2) return;
    int s, d;
    if (e < EE) { s = src[e]; d = dst[e]; } else { s = e - EE; d = e - EE; }
    int pos = atomicAdd(&g_cursor[d], 1);
    g_csrsrc[pos] = s;
}

// ---------------- node encoder: xa@W + b -> LN -> relu ----------------
__global__ void k_encoder(const float* __restrict__ x, const int* __restrict__ shock,
                          const float* __restrict__ W, const float* __restrict__ b,
                          const float* __restrict__ lng, const float* __restrict__ lnb,
                          float* __restrict__ hout) {
    int n = blockIdx.x;
    int t = threadIdx.x;
    __shared__ float xa[18];
    __shared__ float r1[4], r2[4];
    if (t < 16)      xa[t]  = x[n * 16 + t];
    else if (t == 16) xa[16] = (float)shock[n];
    else if (t == 17) xa[17] = (float)g_down[n];
    __syncthreads();
    float v = b[t];
#pragma unroll
    for (int j = 0; j < 18; j++) v += xa[j] * W[j * HD + t];
    float s = v, s2 = v * v;
    for (int off = 16; off > 0; off >>= 1) {
        s  += __shfl_down_sync(0xffffffffu, s,  off);
        s2 += __shfl_down_sync(0xffffffffu, s2, off);
    }
    if ((t & 31) == 0) { r1[t >> 5] = s; r2[t >> 5] = s2; }
    __syncthreads();
    float mu  = (r1[0] + r1[1] + r1[2] + r1[3]) * (1.0f / HD);
    float var = (r2[0] + r2[1] + r2[2] + r2[3]) * (1.0f / HD) - mu * mu;
    float y = (v - mu) * rsqrtf(var + 1e-5f) * lng[t] + lnb[t];
    hout[n * HD + t] = fmaxf(y, 0.0f);
}

// ---------------- weight prep ----------------
__global__ void k_watt(const float* __restrict__ gw,
                       const float* __restrict__ as_, const float* __restrict__ ad_) {
    int l = blockIdx.x, h = blockIdx.y;
    int k = threadIdx.x;
    __shared__ float s_as[128], s_ad[128];
    s_as[k] = as_[(l * 4 + h) * 128 + k];
    s_ad[k] = ad_[(l * 4 + h) * 128 + k];
    __syncthreads();
    const float* wrow = gw + ((size_t)l * 128 + k) * 512 + h * 128;
    float ss = 0.0f, sd = 0.0f;
#pragma unroll 8
    for (int cc = 0; cc < 128; cc++) {
        float w = wrow[cc];
        ss += w * s_as[cc];
        sd += w * s_ad[cc];
    }
    g_wsrc[(l * 4 + h) * 128 + k] = ss;
    g_wdst[(l * 4 + h) * 128 + k] = sd;
}

// fp16 weights, [cout][kk] layout: wh[l][cout][kk] = 0.25*W[l][kk&127][(kk>>7)*128+cout]
__global__ void k_permw_h(const float* __restrict__ gw) {
    int l = blockIdx.x;
    int kk = blockIdx.y;           // 0..511
    int cout = threadIdx.x;        // 0..127
    int k_in = kk & 127, hd = kk >> 7;
    float v = 0.25f * gw[((size_t)l * 128 + k_in) * 512 + (hd << 7) + cout];
    g_wpermh[((size_t)l * 128 + cout) * 512 + kk] = __float2half(v);
}

// edge-MLP first-layer weights, fp16 [n][k]: emp[n][k] = em1_w[k][n]; emq[n][k] = em1_w[128+k][n]
__global__ void k_prep_em(const float* __restrict__ em1w) {
    int n = blockIdx.x;
    int k = threadIdx.x;
    g_emp[n * 128 + k] = __float2half(em1w[(size_t)k * 128 + n]);
    g_emq[n * 128 + k] = __float2half(em1w[(size_t)(128 + k) * 128 + n]);
}

__global__ void k_bnprep(const float* __restrict__ bias, const float* __restrict__ bng,
                         const float* __restrict__ bnb, const float* __restrict__ bnm,
                         const float* __restrict__ bnv) {
    int l = blockIdx.x, c = threadIdx.x;
    int i = l * 128 + c;
    float sc = bng[i] * rsqrtf(bnv[i] + 1e-5f);
    g_bnscale[i] = sc;
    g_bnshift[i] = (bias[i] - bnm[i]) * sc + bnb[i];
}

// ---------------- fp16 tensor-core GEMM: C[M,128] = A[M,K] @ B^T (B fp16 [128][K]) ----
// 128x128 tile, BK=32, 256 thr = 8 warps (2M x 4N), warp tile 64x32, m16n8k16.
__device__ __forceinline__ void mma_f16(float* d, const uint32_t* a, const uint32_t* b) {
    asm volatile(
        "mma.sync.aligned.m16n8k16.row.col.f32.f16.f16.f32 "
        "{%0,%1,%2,%3}, {%4,%5,%6,%7}, {%8,%9}, {%0,%1,%2,%3};\n"
        : "+f"(d[0]), "+f"(d[1]), "+f"(d[2]), "+f"(d[3])
        : "r"(a[0]), "r"(a[1]), "r"(a[2]), "r"(a[3]), "r"(b[0]), "r"(b[1]));
}

__global__ __launch_bounds__(256) void gemm_f16(const float* __restrict__ A,
                                                const __half* __restrict__ B,
                                                float* __restrict__ C,
                                                int M, int K,
                                                const float* __restrict__ escale,
                                                const float* __restrict__ eshift,
                                                int do_relu) {
    __shared__ __align__(16) __half As[128][40];
    __shared__ __align__(16) __half Bs[128][40];
    int tid = threadIdx.x;
    int m0 = blockIdx.x * 128;
    int lane = tid & 31, wid = tid >> 5;
    int mbase = (wid & 1) * 64;
    int nbase = (wid >> 1) * 32;
    int gid = lane >> 2, tg = lane & 3;

    float acc[4][4][4];
#pragma unroll
    for (int i = 0; i < 4; i++)
#pragma unroll
        for (int j = 0; j < 4; j++)
#pragma unroll
            for (int q = 0; q < 4; q++) acc[i][j][q] = 0.0f;

    for (int kc = 0; kc < K; kc += 32) {
        __syncthreads();
        // A tile: 128 rows x 32 k floats -> halves (4 float4 loads per thread)
#pragma unroll
        for (int i = 0; i < 4; i++) {
            int l4 = tid + i * 256;
            int row = l4 >> 3, c4 = (l4 & 7) << 2;
            float4 v = make_float4(0.f, 0.f, 0.f, 0.f);
            int gr = m0 + row;
            if (gr < M) v = *(const float4*)&A[(size_t)gr * K + kc + c4];
            __half2 h01 = __floats2half2_rn(v.x, v.y);
            __half2 h23 = __floats2half2_rn(v.z, v.w);
            *(__half2*)&As[row][c4]     = h01;
            *(__half2*)&As[row][c4 + 2] = h23;
        }
        // B tile: 128 n x 32 k halves (uint4 = 8 halves; 2 per thread)
#pragma unroll
        for (int i = 0; i < 2; i++) {
            int l = tid + i * 256;
            int n = l >> 2, k8 = (l & 3) << 3;
            uint4 v = *(const uint4*)&B[(size_t)n * K + kc + k8];
            *(uint4*)&Bs[n][k8] = v;
        }
        __syncthreads();

#pragma unroll
        for (int k0 = 0; k0 < 32; k0 += 16) {
            uint32_t af[4][4], bf[4][2];
#pragma unroll
            for (int am = 0; am < 4; am++) {
                int row0 = mbase + am * 16 + gid;
                af[am][0] = *(const uint32_t*)&As[row0][k0 + tg * 2];
                af[am][1] = *(const uint32_t*)&As[row0 + 8][k0 + tg * 2];
                af[am][2] = *(const uint32_t*)&As[row0][k0 + tg * 2 + 8];
                af[am][3] = *(const uint32_t*)&As[row0 + 8][k0 + tg * 2 + 8];
            }
#pragma unroll
            for (int an = 0; an < 4; an++) {
                int n0 = nbase + an * 8 + gid;
                bf[an][0] = *(const uint32_t*)&Bs[n0][k0 + tg * 2];
                bf[an][1] = *(const uint32_t*)&Bs[n0][k0 + tg * 2 + 8];
            }
#pragma unroll
            for (int am = 0; am < 4; am++)
#pragma unroll
                for (int an = 0; an < 4; an++)
                    mma_f16(acc[am][an], af[am], bf[an]);
        }
    }

#pragma unroll
    for (int am = 0; am < 4; am++) {
        int row = m0 + mbase + am * 16 + gid;
#pragma unroll
        for (int an = 0; an < 4; an++) {
            int col = nbase + an * 8 + 2 * tg;
            float v0 = acc[am][an][0], v1 = acc[am][an][1];
            float v2 = acc[am][an][2], v3 = acc[am][an][3];
            if (escale) {
                float s0 = escale[col], s1 = escale[col + 1];
                float h0 = eshift[col], h1 = eshift[col + 1];
                v0 = v0 * s0 + h0; v1 = v1 * s1 + h1;
                v2 = v2 * s0 + h0; v3 = v3 * s1 + h1;
                if (do_relu) {
                    v0 = fmaxf(v0, 0.f); v1 = fmaxf(v1, 0.f);
                    v2 = fmaxf(v2, 0.f); v3 = fmaxf(v3, 0.f);
                }
            }
            if (row < M)
                *(float2*)&C[(size_t)row * 128 + col] = make_float2(v0, v1);
            if (row + 8 < M)
                *(float2*)&C[(size_t)(row + 8) * 128 + col] = make_float2(v2, v3);
        }
    }
}

// ---------------- logits from h directly: als = h @ Wa ----------------
__global__ void k_logits2(const float* __restrict__ h, int l) {
    int node = blockIdx.x * 4 + (threadIdx.x >> 5);
    int lane = threadIdx.x & 31;
    if (node >= NN) return;
    float4 hv = *(const float4*)&h[(size_t)node * HD + lane * 4];
#pragma unroll
    for (int hh = 0; hh < 4; hh++) {
        float4 ws = *(const float4*)&g_wsrc[(l * 4 + hh) * 128 + lane * 4];
        float4 wd = *(const float4*)&g_wdst[(l * 4 + hh) * 128 + lane * 4];
        float ds = hv.x * ws.x + hv.y * ws.y + hv.z * ws.z + hv.w * ws.w;
        float dd = hv.x * wd.x + hv.y * wd.y + hv.z * wd.z + hv.w * wd.w;
#pragma unroll
        for (int off = 16; off > 0; off >>= 1) {
            ds += __shfl_down_sync(0xffffffffu, ds, off);
            dd += __shfl_down_sync(0xffffffffu, dd, off);
        }
        if (lane == 0) { g_als[node * 4 + hh] = ds; g_ald[node * 4 + hh] = dd; }
    }
}

// ------- gather v2: softmax over edges, aggregate h[src] per head -> agg[N,512] -------
__global__ void k_gather2(const float* __restrict__ h, float* __restrict__ agg) {
    int node = blockIdx.x * 4 + (threadIdx.x >> 5);
    int lane = threadIdx.x & 31;
    if (node >= NN) return;
    int beg = g_rowptr[node], end = g_rowptr[node + 1];
    float4 ald4 = *(const float4*)&g_ald[node * 4];

    float4 mx = make_float4(-1e30f, -1e30f, -1e30f, -1e30f);
    for (int i = beg + lane; i < end; i += 32) {
        int s = g_csrsrc[i];
        float4 a = *(const float4*)&g_als[s * 4];
        a.x += ald4.x; a.y += ald4.y; a.z += ald4.z; a.w += ald4.w;
        a.x = (a.x >= 0.f) ? a.x : 0.2f * a.x;
        a.y = (a.y >= 0.f) ? a.y : 0.2f * a.y;
        a.z = (a.z >= 0.f) ? a.z : 0.2f * a.z;
        a.w = (a.w >= 0.f) ? a.w : 0.2f * a.w;
        mx.x = fmaxf(mx.x, a.x); mx.y = fmaxf(mx.y, a.y);
        mx.z = fmaxf(mx.z, a.z); mx.w = fmaxf(mx.w, a.w);
    }
#pragma unroll
    for (int off = 16; off > 0; off >>= 1) {
        mx.x = fmaxf(mx.x, __shfl_xor_sync(0xffffffffu, mx.x, off));
        mx.y = fmaxf(mx.y, __shfl_xor_sync(0xffffffffu, mx.y, off));
        mx.z = fmaxf(mx.z, __shfl_xor_sync(0xffffffffu, mx.z, off));
        mx.w = fmaxf(mx.w, __shfl_xor_sync(0xffffffffu, mx.w, off));
    }

    float4 acc0 = make_float4(0, 0, 0, 0), acc1 = acc0, acc2 = acc0, acc3 = acc0;
    float4 sum = make_float4(0, 0, 0, 0);
    for (int i = beg; i < end; i++) {
        int s = g_csrsrc[i];
        float4 a = *(const float4*)&g_als[s * 4];
        a.x += ald4.x; a.y += ald4.y; a.z += ald4.z; a.w += ald4.w;
        a.x = (a.x >= 0.f) ? a.x : 0.2f * a.x;
        a.y = (a.y >= 0.f) ? a.y : 0.2f * a.y;
        a.z = (a.z >= 0.f) ? a.z : 0.2f * a.z;
        a.w = (a.w >= 0.f) ? a.w : 0.2f * a.w;
        float w0 = expf(a.x - mx.x), w1 = expf(a.y - mx.y);
        float w2 = expf(a.z - mx.z), w3 = expf(a.w - mx.w);
        sum.x += w0; sum.y += w1; sum.z += w2; sum.w += w3;
        float4 v = *(const float4*)&h[(size_t)s * HD + lane * 4];
        acc0.x += w0 * v.x; acc0.y += w0 * v.y; acc0.z += w0 * v.z; acc0.w += w0 * v.w;
        acc1.x += w1 * v.x; acc1.y += w1 * v.y; acc1.z += w1 * v.z; acc1.w += w1 * v.w;
        acc2.x += w2 * v.x; acc2.y += w2 * v.y; acc2.z += w2 * v.z; acc2.w += w2 * v.w;
        acc3.x += w3 * v.x; acc3.y += w3 * v.y; acc3.z += w3 * v.z; acc3.w += w3 * v.w;
    }
    float i0 = 1.0f / (sum.x + 1e-16f);
    float i1 = 1.0f / (sum.y + 1e-16f);
    float i2 = 1.0f / (sum.z + 1e-16f);
    float i3 = 1.0f / (sum.w + 1e-16f);
    float* ap = agg + (size_t)node * 512 + lane * 4;
    *(float4*)(ap)       = make_float4(acc0.x * i0, acc0.y * i0, acc0.z * i0, acc0.w * i0);
    *(float4*)(ap + 128) = make_float4(acc1.x * i1, acc1.y * i1, acc1.z * i1, acc1.w * i1);
    *(float4*)(ap + 256) = make_float4(acc2.x * i2, acc2.y * i2, acc2.z * i2, acc2.w * i2);
    *(float4*)(ap + 384) = make_float4(acc3.x * i3, acc3.y * i3, acc3.z * i3, acc3.w * i3);
}

// ------- fused edge MLP v2: 16 edges/block, register-tiled z1@W2 ---------------
__global__ __launch_bounds__(256) void k_edge_mlp2(
        const int* __restrict__ src, const int* __restrict__ dst,
        const float* __restrict__ eattr,
        const float* __restrict__ em1b, const float* __restrict__ wc,
        const float* __restrict__ lng, const float* __restrict__ lnb,
        const float* __restrict__ w2, const float* __restrict__ b2,
        const float* __restrict__ w3, const float* __restrict__ b3,
        float* __restrict__ out) {
    __shared__ float sz1[16][128];
    __shared__ float spart[4][16][64];
    __shared__ float sea[2][8];
    __shared__ float red1[2][4], red2[2][4];

    int tid = threadIdx.x;
    int e_base = blockIdx.x * 16;
    int t = tid & 127, half = tid >> 7;

    for (int g = 0; g < 8; g++) {
        int el = g * 2 + half;
        int e = e_base + el;
        int s = src[e], d = dst[e];
        if (t < 8) sea[half][t] = eattr[e * 8 + t];
        __syncthreads();
        float v = g_p[s * HD + t] + g_q[d * HD + t] + em1b[t];
#pragma unroll
        for (int j = 0; j < 8; j++) v += sea[half][j] * wc[j * HD + t];
        float su = v, sq = v * v;
#pragma unroll
        for (int off = 16; off > 0; off >>= 1) {
            su += __shfl_down_sync(0xffffffffu, su, off);
            sq += __shfl_down_sync(0xffffffffu, sq, off);
        }
        if ((t & 31) == 0) { red1[half][t >> 5] = su; red2[half][t >> 5] = sq; }
        __syncthreads();
        float mu  = (red1[half][0] + red1[half][1] + red1[half][2] + red1[half][3]) * (1.0f / HD);
        float var = (red2[half][0] + red2[half][1] + red2[half][2] + red2[half][3]) * (1.0f / HD) - mu * mu;
        float y = (v - mu) * rsqrtf(var + 1e-5f) * lng[t] + lnb[t];
        sz1[el][t] = fmaxf(y, 0.0f);
    }
    __syncthreads();

    {
        int o4 = (tid & 15) * 4;
        int eg = (tid >> 4) & 3;
        int ks = tid >> 6;
        float4 a0 = make_float4(0, 0, 0, 0), a1 = a0, a2 = a0, a3 = a0;
        int kbeg = ks * 32;
#pragma unroll 8
        for (int k = kbeg; k < kbeg + 32; k++) {
            float4 w4 = *(const float4*)&w2[k * 64 + o4];
            float z0 = sz1[eg * 4 + 0][k];
            float z1v = sz1[eg * 4 + 1][k];
            float z2v = sz1[eg * 4 + 2][k];
            float z3v = sz1[eg * 4 + 3][k];
            a0.x += z0 * w4.x;  a0.y += z0 * w4.y;  a0.z += z0 * w4.z;  a0.w += z0 * w4.w;
            a1.x += z1v * w4.x; a1.y += z1v * w4.y; a1.z += z1v * w4.z; a1.w += z1v * w4.w;
            a2.x += z2v * w4.x; a2.y += z2v * w4.y; a2.z += z2v * w4.z; a2.w += z2v * w4.w;
            a3.x += z3v * w4.x; a3.y += z3v * w4.y; a3.z += z3v * w4.z; a3.w += z3v * w4.w;
        }
        *(float4*)&spart[ks][eg * 4 + 0][o4] = a0;
        *(float4*)&spart[ks][eg * 4 + 1][o4] = a1;
        *(float4*)&spart[ks][eg * 4 + 2][o4] = a2;
        *(float4*)&spart[ks][eg * 4 + 3][o4] = a3;
    }
    __syncthreads();

    {
        int e2 = tid >> 4;
        int ob = (tid & 15) * 4;
        float val = 0.0f;
#pragma unroll
        for (int i = 0; i < 4; i++) {
            int o = ob + i;
            float ssum = spart[0][e2][o] + spart[1][e2][o] + spart[2][e2][o] + spart[3][e2][o];
            float z2 = fmaxf(ssum + b2[o], 0.0f);
            val += z2 * w3[o];
        }
#pragma unroll
        for (int off = 8; off > 0; off >>= 1)
            val += __shfl_down_sync(0xffffffffu, val, off, 16);
        if ((tid & 15) == 0) out[e_base + e2] = val + b3[0];
    }
}

// ---------------- launch ----------------
extern "C" void kernel_launch(void* const* d_in, const int* in_sizes, int n_in,
                              void* d_out, int out_size) {
    const float* x       = (const float*)d_in[0];
    const int*   ei      = (const int*)d_in[1];
    const float* eattr   = (const float*)d_in[2];
    const int*   shock   = (const int*)d_in[3];
    const float* enc_w   = (const float*)d_in[4];
    const float* enc_b   = (const float*)d_in[5];
    const float* enc_lng = (const float*)d_in[6];
    const float* enc_lnb = (const float*)d_in[7];
    const float* gat_w   = (const float*)d_in[8];
    const float* att_src = (const float*)d_in[9];
    const float* att_dst = (const float*)d_in[10];
    const float* gat_bias= (const float*)d_in[11];
    const float* bn_g    = (const float*)d_in[12];
    const float* bn_b    = (const float*)d_in[13];
    const float* bn_m    = (const float*)d_in[14];
    const float* bn_v    = (const float*)d_in[15];
    const float* em1_w   = (const float*)d_in[16];
    const float* em1_b   = (const float*)d_in[17];
    const float* em_lng  = (const float*)d_in[18];
    const float* em_lnb  = (const float*)d_in[19];
    const float* em2_w   = (const float*)d_in[20];
    const float* em2_b   = (const float*)d_in[21];
    const float* em3_w   = (const float*)d_in[22];
    const float* em3_b   = (const float*)d_in[23];
    const int* src = ei;
    const int* dst = ei + EE;
    float* out = (float*)d_out;

    float *ph, *ph2, *pagg, *pp, *pq, *pbnsc, *pbnsh;
    __half *pwh, *pemp, *pemq;
    cudaGetSymbolAddress((void**)&ph,    g_h);
    cudaGetSymbolAddress((void**)&ph2,   g_h2);
    cudaGetSymbolAddress((void**)&pagg,  g_agg);
    cudaGetSymbolAddress((void**)&pp,    g_p);
    cudaGetSymbolAddress((void**)&pq,    g_q);
    cudaGetSymbolAddress((void**)&pwh,   g_wpermh);
    cudaGetSymbolAddress((void**)&pemp,  g_emp);
    cudaGetSymbolAddress((void**)&pemq,  g_emq);
    cudaGetSymbolAddress((void**)&pbnsc, g_bnscale);
    cudaGetSymbolAddress((void**)&pbnsh, g_bnshift);

    // prep (encoder placed at launch slot 4 so ncu -s5 captures a real kernel)
    k_zero_misc<<<(NN + 255) / 256, 256>>>();
    k_down<<<(EE + 255) / 256, 256>>>(src, dst, shock);
    k_count<<<(E2 + 255) / 256, 256>>>(dst);
    k_encoder<<<NN, 128>>>(x, shock, enc_w, enc_b, enc_lng, enc_lnb, ph);
    int nb = (NN + 1023) / 1024;
    k_scan1<<<nb, 1024>>>();
    k_scan2<<<1, 32>>>(nb);
    k_scan3<<<(NN + 255) / 256, 256>>>();
    k_scatter<<<(E2 + 255) / 256, 256>>>(src, dst);

    // weight prep
    k_watt<<<dim3(3, 4), 128>>>(gat_w, att_src, att_dst);
    k_permw_h<<<dim3(3, 512), 128>>>(gat_w);
    k_prep_em<<<128, 128>>>(em1_w);
    k_bnprep<<<3, 128>>>(gat_bias, bn_g, bn_b, bn_m, bn_v);

    // 3 GAT layers: logits -> aggregate h -> fp16 GEMM(+BN fused)
    float* hin = ph;
    float* hout = ph2;
    int gx = (NN + 127) / 128;
    for (int l = 0; l < 3; l++) {
        k_logits2<<<(NN + 3) / 4, 128>>>(hin, l);
        k_gather2<<<(NN + 3) / 4, 128>>>(hin, pagg);
        gemm_f16<<<gx, 256>>>(pagg, pwh + (size_t)l * 128 * 512, hout, NN, 512,
                              pbnsc + l * 128, pbnsh + l * 128, (l < 2) ? 1 : 0);
        float* tmp = hin; hin = hout; hout = tmp;
    }
    // hin now holds the final node embeddings

    // edge MLP first layer factored: p = h @ W_a, q = h @ W_b
    gemm_f16<<<gx, 256>>>(hin, pemp, pp, NN, 128, nullptr, nullptr, 0);
    gemm_f16<<<gx, 256>>>(hin, pemq, pq, NN, 128, nullptr, nullptr, 0);

    // fused edge predictor (EE = 12500 * 16 exactly)
    k_edge_mlp2<<<EE / 16, 256>>>(src, dst, eattr, em1_b, em1_w + 256 * HD,
                                  em_lng, em_lnb, em2_w, em2_b, em3_w, em3_b, out);
}

// round 10
// speedup vs baseline: 1.6320x; 1.4684x over previous
#include <cuda_runtime.h>
#include <cuda_bf16.h>
#include <cuda_fp16.h>
#include <math.h>
#include <stdint.h>

#define NN 50000
#define EE 200000
#define E2 (EE + NN)
#define HD 128

// ---------------- scratch (static device globals; no allocation) ----------------
__device__ int   g_down[NN];
__device__ __align__(16) float g_h[NN * HD];
__device__ __align__(16) float g_h2[NN * HD];
__device__ __align__(16) __half g_aggh[(size_t)NN * 512];
__device__ __align__(16) float g_als[NN * 4];
__device__ __align__(16) float g_ald[NN * 4];
__device__ int   g_cnt[NN];
__device__ int   g_rowtmp[NN];
__device__ int   g_bsum[64];
__device__ int   g_rowptr[NN + 1];
__device__ int   g_cursor[NN];
__device__ int   g_csrsrc[E2];
__device__ __align__(16) __half g_ph[NN * HD];
__device__ __align__(16) __half g_qh[NN * HD];
__device__ __align__(16) __half g_z1[(size_t)(EE + 128) * HD];
__device__ __align__(16) float g_wsrc[3 * 4 * 128];
__device__ __align__(16) float g_wdst[3 * 4 * 128];
__device__ __align__(16) __half g_wpermh[3 * 128 * 512];  // [l][cout][kk]
__device__ __align__(16) __half g_emp[128 * 128];         // [n][k]
__device__ __align__(16) __half g_emq[128 * 128];         // [n][k]
__device__ __align__(16) __half g_emw2h[64 * 128];        // [n][k]
__device__ __align__(16) float g_bnscale[3 * 128];
__device__ __align__(16) float g_bnshift[3 * 128];

__device__ __forceinline__ uint32_t f22u(float a, float b) {
    __half2 h = __floats2half2_rn(a, b);
    return *(uint32_t*)&h;
}

// ---------------- small helpers ----------------
__global__ void k_zero_misc() {
    int i = blockIdx.x * blockDim.x + threadIdx.x;
    if (i < NN) { g_down[i] = 0; g_cnt[i] = 0; }
}

// merged down-flag + degree count
__global__ void k_downcount(const int* __restrict__ src, const int* __restrict__ dst,
                            const int* __restrict__ shock) {
    int e = blockIdx.x * blockDim.x + threadIdx.x;
    if (e >= E2) return;
    if (e < EE) {
        int s = src[e], d = dst[e];
        if (shock[s] != 0) g_down[d] = 1;
        atomicAdd(&g_cnt[d], 1);
    } else {
        atomicAdd(&g_cnt[e - EE], 1);
    }
}

__global__ void k_scan1() {
    __shared__ int sh[1024];
    int tid = threadIdx.x;
    int i = blockIdx.x * 1024 + tid;
    int v = (i < NN) ? g_cnt[i] : 0;
    sh[tid] = v;
    __syncthreads();
    for (int off = 1; off < 1024; off <<= 1) {
        int t = (tid >= off) ? sh[tid - off] : 0;
        __syncthreads();
        sh[tid] += t;
        __syncthreads();
    }
    int incl = sh[tid];
    if (i < NN) g_rowtmp[i] = incl - v;
    if (tid == 1023) g_bsum[blockIdx.x] = incl;
}

__global__ void k_scan2(int nb) {
    if (threadIdx.x == 0 && blockIdx.x == 0) {
        int acc = 0;
        for (int b = 0; b < nb; b++) { int t = g_bsum[b]; g_bsum[b] = acc; acc += t; }
    }
}

__global__ void k_scan3() {
    int i = blockIdx.x * blockDim.x + threadIdx.x;
    if (i >= NN) return;
    int r = g_rowtmp[i] + g_bsum[i >> 10];
    g_rowptr[i] = r;
    g_cursor[i] = r;
    if (i == NN - 1) g_rowptr[NN] = E2;
}

__global__ void k_scatter(const int* __restrict__ src, const int* __restrict__ dst) {
    int e = blockIdx.x * blockDim.x + threadIdx.x;
    if (e >= E2) return;
    int s, d;
    if (e < EE) { s = src[e]; d = dst[e]; } else { s = e - EE; d = e - EE; }
    int pos = atomicAdd(&g_cursor[d], 1);
    g_csrsrc[pos] = s;
}

// ---------------- node encoder v2: 64 nodes/block, W in smem, warp-per-node ----
__global__ __launch_bounds__(256) void k_encoder2(
        const float* __restrict__ x, const int* __restrict__ shock,
        const float* __restrict__ W, const float* __restrict__ b,
        const float* __restrict__ lng, const float* __restrict__ lnb,
        float* __restrict__ hout) {
    __shared__ __align__(16) float Ws[18][128];
    __shared__ __align__(16) float bs[128], gs[128], os[128];
    int tid = threadIdx.x;
    // cooperative load: W = 576 float4, b/lng/lnb = 96 float4
#pragma unroll
    for (int i = 0; i < 3; i++) {
        int idx = tid + i * 256;
        if (idx < 576) ((float4*)Ws)[idx] = ((const float4*)W)[idx];
    }
    if (tid < 128) { bs[tid] = b[tid]; gs[tid] = lng[tid]; os[tid] = lnb[tid]; }
    __syncthreads();

    int w = tid >> 5, lane = tid & 31;
#pragma unroll
    for (int it = 0; it < 8; it++) {
        int n = blockIdx.x * 64 + it * 8 + w;
        if (n >= NN) continue;
        const float4* xr = (const float4*)(x + n * 16);
        float4 x0 = xr[0], x1 = xr[1], x2 = xr[2], x3 = xr[3];
        float sh_ = (float)shock[n];
        float dn_ = (float)g_down[n];
        float xa[16] = {x0.x, x0.y, x0.z, x0.w, x1.x, x1.y, x1.z, x1.w,
                        x2.x, x2.y, x2.z, x2.w, x3.x, x3.y, x3.z, x3.w};
        int c = lane * 4;
        float4 v = *(const float4*)&bs[c];
#pragma unroll
        for (int j = 0; j < 16; j++) {
            float4 w4 = *(const float4*)&Ws[j][c];
            v.x += xa[j] * w4.x; v.y += xa[j] * w4.y;
            v.z += xa[j] * w4.z; v.w += xa[j] * w4.w;
        }
        {
            float4 w4 = *(const float4*)&Ws[16][c];
            v.x += sh_ * w4.x; v.y += sh_ * w4.y; v.z += sh_ * w4.z; v.w += sh_ * w4.w;
            float4 w5 = *(const float4*)&Ws[17][c];
            v.x += dn_ * w5.x; v.y += dn_ * w5.y; v.z += dn_ * w5.z; v.w += dn_ * w5.w;
        }
        float su = v.x + v.y + v.z + v.w;
        float sq = v.x * v.x + v.y * v.y + v.z * v.z + v.w * v.w;
#pragma unroll
        for (int off = 16; off > 0; off >>= 1) {
            su += __shfl_xor_sync(0xffffffffu, su, off);
            sq += __shfl_xor_sync(0xffffffffu, sq, off);
        }
        float mu = su * (1.0f / HD);
        float var = sq * (1.0f / HD) - mu * mu;
        float rs = rsqrtf(var + 1e-5f);
        float4 g4 = *(const float4*)&gs[c];
        float4 o4 = *(const float4*)&os[c];
        float4 y;
        y.x = fmaxf((v.x - mu) * rs * g4.x + o4.x, 0.0f);
        y.y = fmaxf((v.y - mu) * rs * g4.y + o4.y, 0.0f);
        y.z = fmaxf((v.z - mu) * rs * g4.z + o4.z, 0.0f);
        y.w = fmaxf((v.w - mu) * rs * g4.w + o4.w, 0.0f);
        *(float4*)&hout[(size_t)n * HD + c] = y;
    }
}

// ---------------- weight prep ----------------
__global__ void k_watt(const float* __restrict__ gw,
                       const float* __restrict__ as_, const float* __restrict__ ad_) {
    int l = blockIdx.x, h = blockIdx.y;
    int k = threadIdx.x;
    __shared__ float s_as[128], s_ad[128];
    s_as[k] = as_[(l * 4 + h) * 128 + k];
    s_ad[k] = ad_[(l * 4 + h) * 128 + k];
    __syncthreads();
    const float* wrow = gw + ((size_t)l * 128 + k) * 512 + h * 128;
    float ss = 0.0f, sd = 0.0f;
#pragma unroll 8
    for (int cc = 0; cc < 128; cc++) {
        float w = wrow[cc];
        ss += w * s_as[cc];
        sd += w * s_ad[cc];
    }
    g_wsrc[(l * 4 + h) * 128 + k] = ss;
    g_wdst[(l * 4 + h) * 128 + k] = sd;
}

__global__ void k_permw_h(const float* __restrict__ gw) {
    int l = blockIdx.x;
    int kk = blockIdx.y;
    int cout = threadIdx.x;
    int k_in = kk & 127, hd = kk >> 7;
    float v = 0.25f * gw[((size_t)l * 128 + k_in) * 512 + (hd << 7) + cout];
    g_wpermh[((size_t)l * 128 + cout) * 512 + kk] = __float2half(v);
}

// em1 p/q halves [n][k]; em2 half [n][k] (n<64)
__global__ void k_prep_em(const float* __restrict__ em1w, const float* __restrict__ em2w) {
    int n = blockIdx.x;
    int k = threadIdx.x;
    g_emp[n * 128 + k] = __float2half(em1w[(size_t)k * 128 + n]);
    g_emq[n * 128 + k] = __float2half(em1w[(size_t)(128 + k) * 128 + n]);
    if (n < 64) g_emw2h[n * 128 + k] = __float2half(em2w[(size_t)k * 64 + n]);
}

__global__ void k_bnprep(const float* __restrict__ bias, const float* __restrict__ bng,
                         const float* __restrict__ bnb, const float* __restrict__ bnm,
                         const float* __restrict__ bnv) {
    int l = blockIdx.x, c = threadIdx.x;
    int i = l * 128 + c;
    float sc = bng[i] * rsqrtf(bnv[i] + 1e-5f);
    g_bnscale[i] = sc;
    g_bnshift[i] = (bias[i] - bnm[i]) * sc + bnb[i];
}

// ---------------- fp16 tensor-core GEMM: C[M,128] = A[M,K] @ B^T ----------------
// AH: A is fp16 [M][K]; else fp32. OH: C is fp16; else fp32 (with optional BN epi).
__device__ __forceinline__ void mma_f16(float* d, const uint32_t* a, const uint32_t* b) {
    asm volatile(
        "mma.sync.aligned.m16n8k16.row.col.f32.f16.f16.f32 "
        "{%0,%1,%2,%3}, {%4,%5,%6,%7}, {%8,%9}, {%0,%1,%2,%3};\n"
        : "+f"(d[0]), "+f"(d[1]), "+f"(d[2]), "+f"(d[3])
        : "r"(a[0]), "r"(a[1]), "r"(a[2]), "r"(a[3]), "r"(b[0]), "r"(b[1]));
}

template <int AH, int OH>
__global__ __launch_bounds__(256) void gemm_f16(const void* __restrict__ Av,
                                                const __half* __restrict__ B,
                                                void* __restrict__ Cv,
                                                int M, int K,
                                                const float* __restrict__ escale,
                                                const float* __restrict__ eshift,
                                                int do_relu) {
    __shared__ __align__(16) __half As[128][40];
    __shared__ __align__(16) __half Bs[128][40];
    int tid = threadIdx.x;
    int m0 = blockIdx.x * 128;
    int lane = tid & 31, wid = tid >> 5;
    int mbase = (wid & 1) * 64;
    int nbase = (wid >> 1) * 32;
    int gid = lane >> 2, tg = lane & 3;

    float acc[4][4][4];
#pragma unroll
    for (int i = 0; i < 4; i++)
#pragma unroll
        for (int j = 0; j < 4; j++)
#pragma unroll
            for (int q = 0; q < 4; q++) acc[i][j][q] = 0.0f;

    for (int kc = 0; kc < K; kc += 32) {
        __syncthreads();
        if (AH) {
            const __half* A = (const __half*)Av;
#pragma unroll
            for (int i = 0; i < 2; i++) {
                int l4 = tid + i * 256;
                int row = l4 >> 2, c8 = (l4 & 3) << 3;
                uint4 v = make_uint4(0, 0, 0, 0);
                int gr = m0 + row;
                if (gr < M) v = *(const uint4*)&A[(size_t)gr * K + kc + c8];
                *(uint4*)&As[row][c8] = v;
            }
        } else {
            const float* A = (const float*)Av;
#pragma unroll
            for (int i = 0; i < 4; i++) {
                int l4 = tid + i * 256;
                int row = l4 >> 3, c4 = (l4 & 7) << 2;
                float4 v = make_float4(0.f, 0.f, 0.f, 0.f);
                int gr = m0 + row;
                if (gr < M) v = *(const float4*)&A[(size_t)gr * K + kc + c4];
                *(__half2*)&As[row][c4]     = __floats2half2_rn(v.x, v.y);
                *(__half2*)&As[row][c4 + 2] = __floats2half2_rn(v.z, v.w);
            }
        }
#pragma unroll
        for (int i = 0; i < 2; i++) {
            int l = tid + i * 256;
            int n = l >> 2, k8 = (l & 3) << 3;
            uint4 v = *(const uint4*)&B[(size_t)n * K + kc + k8];
            *(uint4*)&Bs[n][k8] = v;
        }
        __syncthreads();

#pragma unroll
        for (int k0 = 0; k0 < 32; k0 += 16) {
            uint32_t af[4][4], bf[4][2];
#pragma unroll
            for (int am = 0; am < 4; am++) {
                int row0 = mbase + am * 16 + gid;
                af[am][0] = *(const uint32_t*)&As[row0][k0 + tg * 2];
                af[am][1] = *(const uint32_t*)&As[row0 + 8][k0 + tg * 2];
                af[am][2] = *(const uint32_t*)&As[row0][k0 + tg * 2 + 8];
                af[am][3] = *(const uint32_t*)&As[row0 + 8][k0 + tg * 2 + 8];
            }
#pragma unroll
            for (int an = 0; an < 4; an++) {
                int n0 = nbase + an * 8 + gid;
                bf[an][0] = *(const uint32_t*)&Bs[n0][k0 + tg * 2];
                bf[an][1] = *(const uint32_t*)&Bs[n0][k0 + tg * 2 + 8];
            }
#pragma unroll
            for (int am = 0; am < 4; am++)
#pragma unroll
                for (int an = 0; an < 4; an++)
                    mma_f16(acc[am][an], af[am], bf[an]);
        }
    }

#pragma unroll
    for (int am = 0; am < 4; am++) {
        int row = m0 + mbase + am * 16 + gid;
#pragma unroll
        for (int an = 0; an < 4; an++) {
            int col = nbase + an * 8 + 2 * tg;
            float v0 = acc[am][an][0], v1 = acc[am][an][1];
            float v2 = acc[am][an][2], v3 = acc[am][an][3];
            if (escale) {
                float s0 = escale[col], s1 = escale[col + 1];
                float h0 = eshift[col], h1 = eshift[col + 1];
                v0 = v0 * s0 + h0; v1 = v1 * s1 + h1;
                v2 = v2 * s0 + h0; v3 = v3 * s1 + h1;
                if (do_relu) {
                    v0 = fmaxf(v0, 0.f); v1 = fmaxf(v1, 0.f);
                    v2 = fmaxf(v2, 0.f); v3 = fmaxf(v3, 0.f);
                }
            }
            if (OH) {
                __half* C = (__half*)Cv;
                if (row < M)     *(uint32_t*)&C[(size_t)row * 128 + col]       = f22u(v0, v1);
                if (row + 8 < M) *(uint32_t*)&C[(size_t)(row + 8) * 128 + col] = f22u(v2, v3);
            } else {
                float* C = (float*)Cv;
                if (row < M)     *(float2*)&C[(size_t)row * 128 + col]       = make_float2(v0, v1);
                if (row + 8 < M) *(float2*)&C[(size_t)(row + 8) * 128 + col] = make_float2(v2, v3);
            }
        }
    }
}

// ---------------- logits from h directly: als = h @ Wa ----------------
__global__ void k_logits2(const float* __restrict__ h, int l) {
    int node = blockIdx.x * 4 + (threadIdx.x >> 5);
    int lane = threadIdx.x & 31;
    if (node >= NN) return;
    float4 hv = *(const float4*)&h[(size_t)node * HD + lane * 4];
#pragma unroll
    for (int hh = 0; hh < 4; hh++) {
        float4 ws = *(const float4*)&g_wsrc[(l * 4 + hh) * 128 + lane * 4];
        float4 wd = *(const float4*)&g_wdst[(l * 4 + hh) * 128 + lane * 4];
        float ds = hv.x * ws.x + hv.y * ws.y + hv.z * ws.z + hv.w * ws.w;
        float dd = hv.x * wd.x + hv.y * wd.y + hv.z * wd.z + hv.w * wd.w;
#pragma unroll
        for (int off = 16; off > 0; off >>= 1) {
            ds += __shfl_down_sync(0xffffffffu, ds, off);
            dd += __shfl_down_sync(0xffffffffu, dd, off);
        }
        if (lane == 0) { g_als[node * 4 + hh] = ds; g_ald[node * 4 + hh] = dd; }
    }
}

// ------- gather: softmax over edges, aggregate h[src] per head -> aggh[N,512] fp16 -------
__global__ void k_gather2(const float* __restrict__ h, __half* __restrict__ aggh) {
    int node = blockIdx.x * 4 + (threadIdx.x >> 5);
    int lane = threadIdx.x & 31;
    if (node >= NN) return;
    int beg = g_rowptr[node], end = g_rowptr[node + 1];
    float4 ald4 = *(const float4*)&g_ald[node * 4];

    float4 mx = make_float4(-1e30f, -1e30f, -1e30f, -1e30f);
    for (int i = beg + lane; i < end; i += 32) {
        int s = g_csrsrc[i];
        float4 a = *(const float4*)&g_als[s * 4];
        a.x += ald4.x; a.y += ald4.y; a.z += ald4.z; a.w += ald4.w;
        a.x = (a.x >= 0.f) ? a.x : 0.2f * a.x;
        a.y = (a.y >= 0.f) ? a.y : 0.2f * a.y;
        a.z = (a.z >= 0.f) ? a.z : 0.2f * a.z;
        a.w = (a.w >= 0.f) ? a.w : 0.2f * a.w;
        mx.x = fmaxf(mx.x, a.x); mx.y = fmaxf(mx.y, a.y);
        mx.z = fmaxf(mx.z, a.z); mx.w = fmaxf(mx.w, a.w);
    }
#pragma unroll
    for (int off = 16; off > 0; off >>= 1) {
        mx.x = fmaxf(mx.x, __shfl_xor_sync(0xffffffffu, mx.x, off));
        mx.y = fmaxf(mx.y, __shfl_xor_sync(0xffffffffu, mx.y, off));
        mx.z = fmaxf(mx.z, __shfl_xor_sync(0xffffffffu, mx.z, off));
        mx.w = fmaxf(mx.w, __shfl_xor_sync(0xffffffffu, mx.w, off));
    }

    float4 acc0 = make_float4(0, 0, 0, 0), acc1 = acc0, acc2 = acc0, acc3 = acc0;
    float4 sum = make_float4(0, 0, 0, 0);
    for (int i = beg; i < end; i++) {
        int s = g_csrsrc[i];
        float4 a = *(const float4*)&g_als[s * 4];
        a.x += ald4.x; a.y += ald4.y; a.z += ald4.z; a.w += ald4.w;
        a.x = (a.x >= 0.f) ? a.x : 0.2f * a.x;
        a.y = (a.y >= 0.f) ? a.y : 0.2f * a.y;
        a.z = (a.z >= 0.f) ? a.z : 0.2f * a.z;
        a.w = (a.w >= 0.f) ? a.w : 0.2f * a.w;
        float w0 = expf(a.x - mx.x), w1 = expf(a.y - mx.y);
        float w2 = expf(a.z - mx.z), w3 = expf(a.w - mx.w);
        sum.x += w0; sum.y += w1; sum.z += w2; sum.w += w3;
        float4 v = *(const float4*)&h[(size_t)s * HD + lane * 4];
        acc0.x += w0 * v.x; acc0.y += w0 * v.y; acc0.z += w0 * v.z; acc0.w += w0 * v.w;
        acc1.x += w1 * v.x; acc1.y += w1 * v.y; acc1.z += w1 * v.z; acc1.w += w1 * v.w;
        acc2.x += w2 * v.x; acc2.y += w2 * v.y; acc2.z += w2 * v.z; acc2.w += w2 * v.w;
        acc3.x += w3 * v.x; acc3.y += w3 * v.y; acc3.z += w3 * v.z; acc3.w += w3 * v.w;
    }
    float i0 = 1.0f / (sum.x + 1e-16f);
    float i1 = 1.0f / (sum.y + 1e-16f);
    float i2 = 1.0f / (sum.z + 1e-16f);
    float i3 = 1.0f / (sum.w + 1e-16f);
    __half* ap = aggh + (size_t)node * 512 + lane * 4;
    *(uint2*)(ap)       = make_uint2(f22u(acc0.x * i0, acc0.y * i0), f22u(acc0.z * i0, acc0.w * i0));
    *(uint2*)(ap + 128) = make_uint2(f22u(acc1.x * i1, acc1.y * i1), f22u(acc1.z * i1, acc1.w * i1));
    *(uint2*)(ap + 256) = make_uint2(f22u(acc2.x * i2, acc2.y * i2), f22u(acc2.z * i2, acc2.w * i2));
    *(uint2*)(ap + 384) = make_uint2(f22u(acc3.x * i3, acc3.y * i3), f22u(acc3.z * i3, acc3.w * i3));
}

// ------- edge LN: warp per edge, z1 = relu(LN(p[s]+q[d]+ea@Wc+b1)) -> fp16 --------
__global__ __launch_bounds__(256) void k_edge_ln(
        const int* __restrict__ src, const int* __restrict__ dst,
        const float* __restrict__ eattr,
        const float* __restrict__ em1b, const float* __restrict__ wc,
        const float* __restrict__ lng, const float* __restrict__ lnb) {
    __shared__ __align__(16) float wcs[8][128];
    __shared__ __align__(16) float b1s[128], gs[128], os[128];
    int tid = threadIdx.x;
    ((float4*)wcs)[tid] = ((const float4*)wc)[tid];   // 1024 floats = 256 float4
    if (tid < 128) { b1s[tid] = em1b[tid]; gs[tid] = lng[tid]; os[tid] = lnb[tid]; }
    __syncthreads();

    int w = tid >> 5, lane = tid & 31;
    int e = blockIdx.x * 8 + w;
    int s = src[e], d = dst[e];
    const float4* ep = (const float4*)(eattr + (size_t)e * 8);
    float4 ea0 = ep[0], ea1 = ep[1];
    float ea[8] = {ea0.x, ea0.y, ea0.z, ea0.w, ea1.x, ea1.y, ea1.z, ea1.w};
    int c = lane * 4;

    uint2 up = *(const uint2*)&g_ph[(size_t)s * HD + c];
    uint2 uq = *(const uint2*)&g_qh[(size_t)d * HD + c];
    float2 p01 = __half22float2(*(__half2*)&up.x);
    float2 p23 = __half22float2(*(__half2*)&up.y);
    float2 q01 = __half22float2(*(__half2*)&uq.x);
    float2 q23 = __half22float2(*(__half2*)&uq.y);
    float4 b4 = *(const float4*)&b1s[c];
    float4 v;
    v.x = p01.x + q01.x + b4.x;
    v.y = p01.y + q01.y + b4.y;
    v.z = p23.x + q23.x + b4.z;
    v.w = p23.y + q23.y + b4.w;
#pragma unroll
    for (int j = 0; j < 8; j++) {
        float4 w4 = *(const float4*)&wcs[j][c];
        v.x += ea[j] * w4.x; v.y += ea[j] * w4.y;
        v.z += ea[j] * w4.z; v.w += ea[j] * w4.w;
    }
    float su = v.x + v.y + v.z + v.w;
    float sq = v.x * v.x + v.y * v.y + v.z * v.z + v.w * v.w;
#pragma unroll
    for (int off = 16; off > 0; off >>= 1) {
        su += __shfl_xor_sync(0xffffffffu, su, off);
        sq += __shfl_xor_sync(0xffffffffu, sq, off);
    }
    float mu = su * (1.0f / HD);
    float var = sq * (1.0f / HD) - mu * mu;
    float rs = rsqrtf(var + 1e-5f);
    float4 g4 = *(const float4*)&gs[c];
    float4 o4 = *(const float4*)&os[c];
    float y0 = fmaxf((v.x - mu) * rs * g4.x + o4.x, 0.0f);
    float y1 = fmaxf((v.y - mu) * rs * g4.y + o4.y, 0.0f);
    float y2 = fmaxf((v.z - mu) * rs * g4.z + o4.z, 0.0f);
    float y3 = fmaxf((v.w - mu) * rs * g4.w + o4.w, 0.0f);
    *(uint2*)&g_z1[(size_t)e * HD + c] = make_uint2(f22u(y0, y1), f22u(y2, y3));
}

// ------- edge GEMM: out[e] = relu(z1[e]@W2 + b2) . w3 + b3, tensor-core ---------
// block = 128 thr = 4 warps; 128 edges/block; warp tile 32 rows x 64 cols.
__global__ __launch_bounds__(128) void k_edge_gemm(
        const float* __restrict__ b2, const float* __restrict__ w3,
        const float* __restrict__ b3, float* __restrict__ out) {
    __shared__ __align__(16) __half z1s[128][136];
    __shared__ __align__(16) __half w2s[64][136];
    int tid = threadIdx.x;
    int r0 = blockIdx.x * 128;
    // z1 tile: 128x128 halves = 2048 uint4
#pragma unroll
    for (int i = 0; i < 16; i++) {
        int idx = tid + i * 128;
        int row = idx >> 4, c8 = (idx & 15) << 3;
        *(uint4*)&z1s[row][c8] = *(const uint4*)&g_z1[(size_t)(r0 + row) * HD + c8];
    }
    // w2 tile: 64x128 halves = 1024 uint4
#pragma unroll
    for (int i = 0; i < 8; i++) {
        int idx = tid + i * 128;
        int row = idx >> 4, c8 = (idx & 15) << 3;
        *(uint4*)&w2s[row][c8] = *(const uint4*)&g_emw2h[(size_t)row * HD + c8];
    }
    __syncthreads();

    int w = tid >> 5, lane = tid & 31;
    int gid = lane >> 2, tg = lane & 3;
    int mwarp = w * 32;

    float acc[2][8][4];
#pragma unroll
    for (int i = 0; i < 2; i++)
#pragma unroll
        for (int j = 0; j < 8; j++)
#pragma unroll
            for (int q = 0; q < 4; q++) acc[i][j][q] = 0.0f;

#pragma unroll
    for (int k0 = 0; k0 < 128; k0 += 16) {
        uint32_t af[2][4], bf[8][2];
#pragma unroll
        for (int am = 0; am < 2; am++) {
            int row0 = mwarp + am * 16 + gid;
            af[am][0] = *(const uint32_t*)&z1s[row0][k0 + tg * 2];
            af[am][1] = *(const uint32_t*)&z1s[row0 + 8][k0 + tg * 2];
            af[am][2] = *(const uint32_t*)&z1s[row0][k0 + tg * 2 + 8];
            af[am][3] = *(const uint32_t*)&z1s[row0 + 8][k0 + tg * 2 + 8];
        }
#pragma unroll
        for (int an = 0; an < 8; an++) {
            int n0 = an * 8 + gid;
            bf[an][0] = *(const uint32_t*)&w2s[n0][k0 + tg * 2];
            bf[an][1] = *(const uint32_t*)&w2s[n0][k0 + tg * 2 + 8];
        }
#pragma unroll
        for (int am = 0; am < 2; am++)
#pragma unroll
            for (int an = 0; an < 8; an++)
                mma_f16(acc[am][an], af[am], bf[an]);
    }

    float b3v = b3[0];
#pragma unroll
    for (int am = 0; am < 2; am++) {
        float r0sum = 0.0f, r1sum = 0.0f;
#pragma unroll
        for (int an = 0; an < 8; an++) {
            int cA = an * 8 + 2 * tg;
            float b2a = b2[cA], b2b = b2[cA + 1];
            float w3a = w3[cA], w3b = w3[cA + 1];
            r0sum += fmaxf(acc[am][an][0] + b2a, 0.0f) * w3a
                   + fmaxf(acc[am][an][1] + b2b, 0.0f) * w3b;
            r1sum += fmaxf(acc[am][an][2] + b2a, 0.0f) * w3a
                   + fmaxf(acc[am][an][3] + b2b, 0.0f) * w3b;
        }
        r0sum += __shfl_down_sync(0xffffffffu, r0sum, 2, 4);
        r0sum += __shfl_down_sync(0xffffffffu, r0sum, 1, 4);
        r1sum += __shfl_down_sync(0xffffffffu, r1sum, 2, 4);
        r1sum += __shfl_down_sync(0xffffffffu, r1sum, 1, 4);
        if (tg == 0) {
            int row = r0 + mwarp + am * 16 + gid;
            if (row < EE)     out[row]     = r0sum + b3v;
            if (row + 8 < EE) out[row + 8] = r1sum + b3v;
        }
    }
}

// ---------------- launch ----------------
extern "C" void kernel_launch(void* const* d_in, const int* in_sizes, int n_in,
                              void* d_out, int out_size) {
    const float* x       = (const float*)d_in[0];
    const int*   ei      = (const int*)d_in[1];
    const float* eattr   = (const float*)d_in[2];
    const int*   shock   = (const int*)d_in[3];
    const float* enc_w   = (const float*)d_in[4];
    const float* enc_b   = (const float*)d_in[5];
    const float* enc_lng = (const float*)d_in[6];
    const float* enc_lnb = (const float*)d_in[7];
    const float* gat_w   = (const float*)d_in[8];
    const float* att_src = (const float*)d_in[9];
    const float* att_dst = (const float*)d_in[10];
    const float* gat_bias= (const float*)d_in[11];
    const float* bn_g    = (const float*)d_in[12];
    const float* bn_b    = (const float*)d_in[13];
    const float* bn_m    = (const float*)d_in[14];
    const float* bn_v    = (const float*)d_in[15];
    const float* em1_w   = (const float*)d_in[16];
    const float* em1_b   = (const float*)d_in[17];
    const float* em_lng  = (const float*)d_in[18];
    const float* em_lnb  = (const float*)d_in[19];
    const float* em2_w   = (const float*)d_in[20];
    const float* em2_b   = (const float*)d_in[21];
    const float* em3_w   = (const float*)d_in[22];
    const float* em3_b   = (const float*)d_in[23];
    const int* src = ei;
    const int* dst = ei + EE;
    float* out = (float*)d_out;

    float *ph, *ph2, *pbnsc, *pbnsh;
    __half *paggh, *pwh, *pemp, *pemq, *pph, *pqh;
    cudaGetSymbolAddress((void**)&ph,    g_h);
    cudaGetSymbolAddress((void**)&ph2,   g_h2);
    cudaGetSymbolAddress((void**)&paggh, g_aggh);
    cudaGetSymbolAddress((void**)&pph,   g_ph);
    cudaGetSymbolAddress((void**)&pqh,   g_qh);
    cudaGetSymbolAddress((void**)&pwh,   g_wpermh);
    cudaGetSymbolAddress((void**)&pemp,  g_emp);
    cudaGetSymbolAddress((void**)&pemq,  g_emq);
    cudaGetSymbolAddress((void**)&pbnsc, g_bnscale);
    cudaGetSymbolAddress((void**)&pbnsh, g_bnshift);

    // graph prep
    k_zero_misc<<<(NN + 255) / 256, 256>>>();
    k_downcount<<<(E2 + 255) / 256, 256>>>(src, dst, shock);
    int nb = (NN + 1023) / 1024;
    k_scan1<<<nb, 1024>>>();
    k_scan2<<<1, 32>>>(nb);
    k_scan3<<<(NN + 255) / 256, 256>>>();
    k_scatter<<<(E2 + 255) / 256, 256>>>(src, dst);

    // node encoder (needs g_down)
    k_encoder2<<<(NN + 63) / 64, 256>>>(x, shock, enc_w, enc_b, enc_lng, enc_lnb, ph);

    // weight prep
    k_watt<<<dim3(3, 4), 128>>>(gat_w, att_src, att_dst);
    k_permw_h<<<dim3(3, 512), 128>>>(gat_w);
    k_prep_em<<<128, 128>>>(em1_w, em2_w);
    k_bnprep<<<3, 128>>>(gat_bias, bn_g, bn_b, bn_m, bn_v);

    // 3 GAT layers
    float* hin = ph;
    float* hout = ph2;
    int gx = (NN + 127) / 128;
    for (int l = 0; l < 3; l++) {
        k_logits2<<<(NN + 3) / 4, 128>>>(hin, l);
        k_gather2<<<(NN + 3) / 4, 128>>>(hin, paggh);
        gemm_f16<1, 0><<<gx, 256>>>(paggh, pwh + (size_t)l * 128 * 512, hout, NN, 512,
                                    pbnsc + l * 128, pbnsh + l * 128, (l < 2) ? 1 : 0);
        float* tmp = hin; hin = hout; hout = tmp;
    }

    // p = h @ W_a, q = h @ W_b  (fp16 outputs)
    gemm_f16<0, 1><<<gx, 256>>>(hin, pemp, pph, NN, 128, nullptr, nullptr, 0);
    gemm_f16<0, 1><<<gx, 256>>>(hin, pemq, pqh, NN, 128, nullptr, nullptr, 0);

    // edge predictor: LN pass then tensor-core GEMM+reduce
    k_edge_ln<<<EE / 8, 256>>>(src, dst, eattr, em1_b, em1_w + 256 * HD, em_lng, em_lnb);
    k_edge_gemm<<<(EE + 127) / 128, 128>>>(em2_b, em3_w, em3_b, out);
}